// round 7
// baseline (speedup 1.0000x reference)
#include <cuda_runtime.h>
#include <cuda_bf16.h>
#include <cstdint>

// InteractionArch via base-ISA tensor cores (mma.sync bf16 x3 emulated fp32).
// tcgen05 is NOT available: harness builds PTX at .target sm_103 (no 'a').
//
// Per CTA (128 thr = 4 warps): 4 batches, one per warp. Each batch row group
// is a padded 32x128 fp32 matrix; split fp32 -> bf16 hi + lo and compute
//   D = H*H^T + H*L^T + L*H^T       (L*L^T ~ 2^-16 rel, dropped)
// with mma.sync.aligned.m16n8k16.row.col.f32.bf16.bf16.f32. Only the upper
// tiles T00 (m0-15,n0-15), T01 (m0-15,n16-31), T11 (m16-31,n16-31) of the
// 32x32 Gram are computed: 18 HMMA per k16-step, 144 per batch.
//
// K processed in 2 stages of 64 -> smem = 4 x (4KB hi + 4KB lo) = 32KB
// -> ~7 CTAs/SM (the fp32 FFMA versions were occupancy-starved).
//
// smem swizzle: 16B chunk c (0..7) of row r stored at chunk position
// c ^ (r & 7) -> every ldmatrix octet (8 rows, same chunk OR same row,
// 8 chunks) hits 8 distinct bank groups. Conflict-free.
//
// Epilogue: per-warp 32x32 staged to smem (stride 33), then one contiguous
// coalesced 4*351-float segment written per CTA.

#define FEAT 27
#define KDIM 128
#define NPAIR 351
#define GROUP 4
#define THREADS 128
#define LO_OFF 16384           // byte offset of lo region in smem
#define STG_STRIDE 33          // staging row stride (floats)
#define STG_WARP 1088          // floats per warp staging area (>= 32*33)

__device__ __forceinline__ void split2(float x, float y, uint32_t& h, uint32_t& l) {
    asm("cvt.rn.satfinite.bf16x2.f32 %0, %1, %2;" : "=r"(h) : "f"(y), "f"(x));
    float hx = __uint_as_float(h << 16);
    float hy = __uint_as_float(h & 0xffff0000u);
    float lx = x - hx, ly = y - hy;
    asm("cvt.rn.satfinite.bf16x2.f32 %0, %1, %2;" : "=r"(l) : "f"(ly), "f"(lx));
}

__device__ __forceinline__ void ldx4(uint32_t addr, uint32_t* r) {
    asm volatile("ldmatrix.sync.aligned.m8n8.x4.shared.b16 {%0,%1,%2,%3}, [%4];"
                 : "=r"(r[0]), "=r"(r[1]), "=r"(r[2]), "=r"(r[3]) : "r"(addr));
}

__device__ __forceinline__ void mma16816(float* c, const uint32_t* a, const uint32_t* b) {
    asm volatile(
        "mma.sync.aligned.m16n8k16.row.col.f32.bf16.bf16.f32 "
        "{%0,%1,%2,%3}, {%4,%5,%6,%7}, {%8,%9}, {%0,%1,%2,%3};"
        : "+f"(c[0]), "+f"(c[1]), "+f"(c[2]), "+f"(c[3])
        : "r"(a[0]), "r"(a[1]), "r"(a[2]), "r"(a[3]), "r"(b[0]), "r"(b[1]));
}

__global__ __launch_bounds__(THREADS)
void interaction_kernel(const float* __restrict__ dense,
                        const float* __restrict__ sparse,
                        float* __restrict__ out,
                        int B)
{
    __shared__ __align__(1024) char smem[32768];

    const int tid = threadIdx.x;
    const int wid = tid >> 5;
    const int lane = tid & 31;
    const long bbase = (long)blockIdx.x * GROUP;

    uint32_t sb;
    asm("{ .reg .u64 t; cvta.to.shared.u64 t, %1; cvt.u32.u64 %0, t; }"
        : "=r"(sb) : "l"((void*)smem));

    // lane-dependent ldmatrix row/chunk selectors
    const int arow = lane & 15;              // A-frag: rows R+(lane&15)
    const int asel = lane >> 4;              //         chunk 2s + asel
    const int brow = (lane & 7) + ((lane & 16) >> 1);   // B-frag rows
    const int bsel = (lane >> 3) & 1;                   // chunk 2s + bsel

    const uint32_t hbase = sb + wid * 4096;  // this warp's batch hi buffer
    const uint32_t lbase = hbase + LO_OFF;

    float acc[6][4] = {};   // T00a,T00b,T01a,T01b,T11a,T11b

#pragma unroll
    for (int s2 = 0; s2 < 2; ++s2) {
        // ---- Load phase (whole CTA): 4 batches x 32 rows x 8 chunks ----
#pragma unroll
        for (int it = 0; it < 8; ++it) {
            const int id = it * THREADS + tid;
            const int g = id >> 8;
            const int r = (id >> 3) & 31;
            const int c = id & 7;
            const long b = bbase + g;

            uint4 hi = make_uint4(0u, 0u, 0u, 0u);
            uint4 lo = make_uint4(0u, 0u, 0u, 0u);
            if (r < FEAT && b < B) {
                const float* src = (r == 0)
                    ? dense + b * KDIM + s2 * 64 + c * 8
                    : sparse + ((b * 26) + (r - 1)) * (long)KDIM + s2 * 64 + c * 8;
                float4 a0 = *reinterpret_cast<const float4*>(src);
                float4 a1 = *reinterpret_cast<const float4*>(src + 4);
                split2(a0.x, a0.y, hi.x, lo.x);
                split2(a0.z, a0.w, hi.y, lo.y);
                split2(a1.x, a1.y, hi.z, lo.z);
                split2(a1.z, a1.w, hi.w, lo.w);
            }
            const int off = g * 4096 + r * 128 + ((c ^ (r & 7)) << 4);
            *reinterpret_cast<uint4*>(smem + off) = hi;
            *reinterpret_cast<uint4*>(smem + LO_OFF + off) = lo;
        }
        __syncthreads();

        // ---- Compute phase: 4 k16-steps over this 64-wide stage ----
#pragma unroll
        for (int s = 0; s < 4; ++s) {
            const int ac = 2 * s + asel;
            const int bc = 2 * s + bsel;

            uint32_t A0h[4], A0l[4], A1h[4], A1l[4];
            uint32_t B0h[4], B0l[4], B1h[4], B1l[4];

            const uint32_t offA0 = arow * 128 + ((ac ^ (arow & 7)) << 4);
            const uint32_t offA1 = (arow + 16) * 128 + ((ac ^ (arow & 7)) << 4);
            const uint32_t offB0 = brow * 128 + ((bc ^ (brow & 7)) << 4);
            const uint32_t offB1 = (brow + 16) * 128 + ((bc ^ (brow & 7)) << 4);

            ldx4(hbase + offA0, A0h);  ldx4(lbase + offA0, A0l);
            ldx4(hbase + offA1, A1h);  ldx4(lbase + offA1, A1l);
            ldx4(hbase + offB0, B0h);  ldx4(lbase + offB0, B0l);
            ldx4(hbase + offB1, B1h);  ldx4(lbase + offB1, B1l);

            // H * H^T
            mma16816(acc[0], A0h, B0h);      mma16816(acc[1], A0h, B0h + 2);
            mma16816(acc[2], A0h, B1h);      mma16816(acc[3], A0h, B1h + 2);
            mma16816(acc[4], A1h, B1h);      mma16816(acc[5], A1h, B1h + 2);
            // H * L^T
            mma16816(acc[0], A0h, B0l);      mma16816(acc[1], A0h, B0l + 2);
            mma16816(acc[2], A0h, B1l);      mma16816(acc[3], A0h, B1l + 2);
            mma16816(acc[4], A1h, B1l);      mma16816(acc[5], A1h, B1l + 2);
            // L * H^T
            mma16816(acc[0], A0l, B0h);      mma16816(acc[1], A0l, B0h + 2);
            mma16816(acc[2], A0l, B1h);      mma16816(acc[3], A0l, B1h + 2);
            mma16816(acc[4], A1l, B1h);      mma16816(acc[5], A1l, B1h + 2);
        }
        __syncthreads();   // all reads done before next stage / staging reuse
    }

    // ---- Stage per-warp 32x32 result into smem (stride 33) ----
    {
        float* stg = reinterpret_cast<float*>(smem) + wid * STG_WARP;
        const int r0 = lane >> 2;
        const int c0 = (lane & 3) * 2;
        const int MR[6] = {0, 0, 0, 0, 16, 16};
        const int NC[6] = {0, 8, 16, 24, 16, 24};
#pragma unroll
        for (int t = 0; t < 6; ++t) {
            const int rr = MR[t] + r0;
            const int cc = NC[t] + c0;
            stg[rr * STG_STRIDE + cc]           = acc[t][0];
            stg[rr * STG_STRIDE + cc + 1]       = acc[t][1];
            stg[(rr + 8) * STG_STRIDE + cc]     = acc[t][2];
            stg[(rr + 8) * STG_STRIDE + cc + 1] = acc[t][3];
        }
    }
    __syncthreads();

    // ---- Coalesced writeout: contiguous 4*351 floats per CTA ----
    const long obase = bbase * NPAIR;
    const long lim = (long)B * NPAIR;
    const float* stg0 = reinterpret_cast<const float*>(smem);
#pragma unroll
    for (int k = 0; k < 11; ++k) {
        const int idx = k * THREADS + tid;
        if (idx < GROUP * NPAIR && obase + idx < lim) {
            const int g = idx / NPAIR;
            const int e = idx - g * NPAIR;
            // invert strict-upper-triangle index e -> (i, j)
            int i = (int)((53.0f - sqrtf(2809.0f - 8.0f * (float)e)) * 0.5f);
            if (i < 0) i = 0;
            if (i > 25) i = 25;
#pragma unroll
            for (int q = 0; q < 2; ++q) {
                if (i < 25 && e >= (i + 1) * (52 - i) / 2) ++i;
                if (i > 0 && e < i * (53 - i) / 2) --i;
            }
            const int cum = i * (53 - i) / 2;
            const int j = i + 1 + (e - cum);
            out[obase + idx] = stg0[g * STG_WARP + i * STG_STRIDE + j];
        }
    }
}

extern "C" void kernel_launch(void* const* d_in, const int* in_sizes, int n_in,
                              void* d_out, int out_size)
{
    const float* dense  = (const float*)d_in[0];   // (B, 128)
    const float* sparse = (const float*)d_in[1];   // (B, 26, 128)
    float* out = (float*)d_out;                    // (B, 351)

    const int B = in_sizes[0] / KDIM;
    const int grid = (B + GROUP - 1) / GROUP;
    interaction_kernel<<<grid, THREADS>>>(dense, sparse, out, B);
}

// round 8
// speedup vs baseline: 1.3378x; 1.3378x over previous
#include <cuda_runtime.h>
#include <cuda_bf16.h>
#include <cstdint>

// InteractionArch via base-ISA tensor cores (mma.sync bf16 x3 emulated fp32).
// tcgen05 unavailable (harness targets sm_103 without the 'a' suffix).
//
// Per CTA (128 thr = 4 warps): 4 batches, one per warp. Padded 32xK per
// batch; split fp32 -> bf16 hi + lo and compute
//   D = H*H^T + H*L^T + L*H^T     (L*L^T ~ 2^-16 rel, dropped)
// via mma.sync.aligned.m16n8k16.row.col.f32.bf16.bf16.f32 on the upper
// tiles T00/T01/T11 only (18 HMMA per k16-step).
//
// K processed in FOUR stages of 32 -> smem = 16 KB -> ~13 CTAs/SM (52
// warps, 81% occ). Round 7 (2 stages of 64, 32 KB) sat at 30% occ and was
// latency-bound with every pipe under 50%.
//
// Swizzle (64 B rows = 4 chunks of 16 B): chunk c of row r stored at
// position c ^ ((r>>1)&3). Granule index mod 8 = 4r + pos is pairwise
// distinct across every octet of 8 rows at fixed c (and across 4 chunks of
// 2 rows), so ldmatrix and STS.128 are conflict-free.

#define FEAT 27
#define KDIM 128
#define NPAIR 351
#define GROUP 4
#define THREADS 128
#define LO_OFF 8192            // byte offset of lo region
#define BATCH_BYTES 2048       // 32 rows x 64 B
#define STG_STRIDE 29
#define STG_WARP 783           // 27 * 29 floats

__device__ __forceinline__ void split2(float x, float y, uint32_t& h, uint32_t& l) {
    asm("cvt.rn.satfinite.bf16x2.f32 %0, %1, %2;" : "=r"(h) : "f"(y), "f"(x));
    float hx = __uint_as_float(h << 16);
    float hy = __uint_as_float(h & 0xffff0000u);
    float lx = x - hx, ly = y - hy;
    asm("cvt.rn.satfinite.bf16x2.f32 %0, %1, %2;" : "=r"(l) : "f"(ly), "f"(lx));
}

__device__ __forceinline__ void ldx4(uint32_t addr, uint32_t* r) {
    asm volatile("ldmatrix.sync.aligned.m8n8.x4.shared.b16 {%0,%1,%2,%3}, [%4];"
                 : "=r"(r[0]), "=r"(r[1]), "=r"(r[2]), "=r"(r[3]) : "r"(addr));
}

__device__ __forceinline__ void mma16816(float* c, const uint32_t* a, const uint32_t* b) {
    asm volatile(
        "mma.sync.aligned.m16n8k16.row.col.f32.bf16.bf16.f32 "
        "{%0,%1,%2,%3}, {%4,%5,%6,%7}, {%8,%9}, {%0,%1,%2,%3};"
        : "+f"(c[0]), "+f"(c[1]), "+f"(c[2]), "+f"(c[3])
        : "r"(a[0]), "r"(a[1]), "r"(a[2]), "r"(a[3]), "r"(b[0]), "r"(b[1]));
}

__global__ __launch_bounds__(THREADS)
void interaction_kernel(const float* __restrict__ dense,
                        const float* __restrict__ sparse,
                        float* __restrict__ out,
                        int B)
{
    __shared__ __align__(1024) char smem[16384];

    const int tid = threadIdx.x;
    const int wid = tid >> 5;
    const int lane = tid & 31;
    const long bbase = (long)blockIdx.x * GROUP;

    uint32_t sb;
    asm("{ .reg .u64 t; cvta.to.shared.u64 t, %1; cvt.u32.u64 %0, t; }"
        : "=r"(sb) : "l"((void*)smem));

    // lane-dependent ldmatrix row/chunk selectors
    const int arow = lane & 15;                         // A rows R + arow
    const int asel = lane >> 4;                         // chunk 2s + asel
    const int brow = (lane & 7) + ((lane & 16) >> 1);   // B rows
    const int bsel = (lane >> 3) & 1;

    const int aswz = (arow >> 1) & 3;   // invariant under +16
    const int bswz = (brow >> 1) & 3;

    const uint32_t hbase = sb + wid * BATCH_BYTES;
    const uint32_t lbase = hbase + LO_OFF;

    // load-phase decomposition: id = it*128 + tid over 512 chunks of 8 floats
    const int lg = tid >> 7;            // always 0 at 128 thr; g from it
    (void)lg;

    float acc[6][4] = {};   // T00a,T00b,T01a,T01b,T11a,T11b

#pragma unroll
    for (int s2 = 0; s2 < 4; ++s2) {
        // ---- Load phase: 4 batches x 32 rows x 4 chunks (8 floats each) ----
#pragma unroll
        for (int it = 0; it < 4; ++it) {
            const int id = it * THREADS + tid;   // 0..511
            const int g = id >> 7;
            const int r = (id >> 2) & 31;
            const int c = id & 3;
            const long b = bbase + g;

            uint4 hi = make_uint4(0u, 0u, 0u, 0u);
            uint4 lo = make_uint4(0u, 0u, 0u, 0u);
            if (r < FEAT && b < B) {
                const float* src = (r == 0)
                    ? dense + b * KDIM + s2 * 32 + c * 8
                    : sparse + ((b * 26) + (r - 1)) * (long)KDIM + s2 * 32 + c * 8;
                float4 a0 = *reinterpret_cast<const float4*>(src);
                float4 a1 = *reinterpret_cast<const float4*>(src + 4);
                split2(a0.x, a0.y, hi.x, lo.x);
                split2(a0.z, a0.w, hi.y, lo.y);
                split2(a1.x, a1.y, hi.z, lo.z);
                split2(a1.z, a1.w, hi.w, lo.w);
            }
            const int off = g * BATCH_BYTES + r * 64 + ((c ^ ((r >> 1) & 3)) << 4);
            *reinterpret_cast<uint4*>(smem + off) = hi;
            *reinterpret_cast<uint4*>(smem + LO_OFF + off) = lo;
        }
        __syncthreads();

        // ---- Compute phase: 2 k16-steps over this 32-wide stage ----
#pragma unroll
        for (int s = 0; s < 2; ++s) {
            const int ac = 2 * s + asel;
            const int bc = 2 * s + bsel;

            uint32_t A0h[4], A0l[4], A1h[4], A1l[4];
            uint32_t B0h[4], B0l[4], B1h[4], B1l[4];

            const uint32_t offA0 = arow * 64 + ((ac ^ aswz) << 4);
            const uint32_t offA1 = (arow + 16) * 64 + ((ac ^ aswz) << 4);
            const uint32_t offB0 = brow * 64 + ((bc ^ bswz) << 4);
            const uint32_t offB1 = (brow + 16) * 64 + ((bc ^ bswz) << 4);

            ldx4(hbase + offA0, A0h);  ldx4(lbase + offA0, A0l);
            ldx4(hbase + offA1, A1h);  ldx4(lbase + offA1, A1l);
            ldx4(hbase + offB0, B0h);  ldx4(lbase + offB0, B0l);
            ldx4(hbase + offB1, B1h);  ldx4(lbase + offB1, B1l);

            // H * H^T
            mma16816(acc[0], A0h, B0h);      mma16816(acc[1], A0h, B0h + 2);
            mma16816(acc[2], A0h, B1h);      mma16816(acc[3], A0h, B1h + 2);
            mma16816(acc[4], A1h, B1h);      mma16816(acc[5], A1h, B1h + 2);
            // H * L^T
            mma16816(acc[0], A0h, B0l);      mma16816(acc[1], A0h, B0l + 2);
            mma16816(acc[2], A0h, B1l);      mma16816(acc[3], A0h, B1l + 2);
            mma16816(acc[4], A1h, B1l);      mma16816(acc[5], A1h, B1l + 2);
            // L * H^T
            mma16816(acc[0], A0l, B0h);      mma16816(acc[1], A0l, B0h + 2);
            mma16816(acc[2], A0l, B1h);      mma16816(acc[3], A0l, B1h + 2);
            mma16816(acc[4], A1l, B1h);      mma16816(acc[5], A1l, B1h + 2);
        }
        __syncthreads();   // reads done before next stage / staging reuse
    }

    // ---- Stage per-warp upper triangle into smem (27 rows, stride 29) ----
    {
        float* stg = reinterpret_cast<float*>(smem) + wid * STG_WARP;
        const int r0 = lane >> 2;
        const int c0 = (lane & 3) * 2;
        const int MR[6] = {0, 0, 0, 0, 16, 16};
        const int NC[6] = {0, 8, 16, 24, 16, 24};
#pragma unroll
        for (int t = 0; t < 6; ++t) {
#pragma unroll
            for (int hrow = 0; hrow < 2; ++hrow) {
                const int rr = MR[t] + r0 + hrow * 8;
                const int cc = NC[t] + c0;
                if (rr < FEAT) {
                    if (cc < 28)     stg[rr * STG_STRIDE + cc]     = acc[t][hrow * 2];
                    if (cc + 1 < 28) stg[rr * STG_STRIDE + cc + 1] = acc[t][hrow * 2 + 1];
                }
            }
        }
    }
    __syncthreads();

    // ---- Coalesced writeout: contiguous 4*351 floats per CTA ----
    const long obase = bbase * NPAIR;
    const long lim = (long)B * NPAIR;
    const float* stg0 = reinterpret_cast<const float*>(smem);
#pragma unroll
    for (int k = 0; k < 11; ++k) {
        const int idx = k * THREADS + tid;
        if (idx < GROUP * NPAIR && obase + idx < lim) {
            const int g = idx / NPAIR;
            const int e = idx - g * NPAIR;
            // invert strict-upper-triangle index e -> (i, j)
            int i = (int)((53.0f - sqrtf(2809.0f - 8.0f * (float)e)) * 0.5f);
            if (i < 0) i = 0;
            if (i > 25) i = 25;
#pragma unroll
            for (int q = 0; q < 2; ++q) {
                if (i < 25 && e >= (i + 1) * (52 - i) / 2) ++i;
                if (i > 0 && e < i * (53 - i) / 2) --i;
            }
            const int cum = i * (53 - i) / 2;
            const int j = i + 1 + (e - cum);
            out[obase + idx] = stg0[g * STG_WARP + i * STG_STRIDE + j];
        }
    }
}

extern "C" void kernel_launch(void* const* d_in, const int* in_sizes, int n_in,
                              void* d_out, int out_size)
{
    const float* dense  = (const float*)d_in[0];   // (B, 128)
    const float* sparse = (const float*)d_in[1];   // (B, 26, 128)
    float* out = (float*)d_out;                    // (B, 351)

    const int B = in_sizes[0] / KDIM;
    const int grid = (B + GROUP - 1) / GROUP;
    interaction_kernel<<<grid, THREADS>>>(dense, sparse, out, B);
}